// round 4
// baseline (speedup 1.0000x reference)
#include <cuda_runtime.h>
#include <cuda_bf16.h>

#define EMBED_D   128
#define TWO_D     256
#define NEG_SLOPE 0.01f

__device__ __forceinline__ float4 ldcs4(const float* p) {
    return __ldcs(reinterpret_cast<const float4*>(p));
}

// One warp per row. Lane octet o = lane>>3 owns segment k=o of the [4,256]
// concate row; within an octet, lane sub = lane&7 covers float4 chunks
// sub*4 + j*32 (j=0..7). Reduction is 3 octet-butterflies + 4 broadcasts.
__global__ __launch_bounds__(256) void gat_kernel(
    const int*   __restrict__ node_type,
    const float* __restrict__ c_agg,      // [N,128]
    const float* __restrict__ concate,    // [N,4,256]
    const float* __restrict__ a_agg,      // [N,128]
    const float* __restrict__ p_agg,      // [N,128]
    const float* __restrict__ v_agg,      // [N,128]
    const float* __restrict__ a_att,      // [256]
    const float* __restrict__ p_att,      // [256]
    const float* __restrict__ v_att,      // [256]
    float*       __restrict__ out,        // [N,128]
    int N)
{
    __shared__ float s_att[TWO_D];

    const int tid = threadIdx.x;

    // Uniform branch: select attention vector by node type; stage in smem.
    const int nt = *node_type;
    const float* att = (nt == 1) ? a_att : (nt == 2) ? p_att : v_att;
    s_att[tid] = att[tid];               // 256 threads <-> 256 floats
    __syncthreads();

    const int lane = tid & 31;
    const int row  = (blockIdx.x * blockDim.x + tid) >> 5;
    if (row >= N) return;

    const int seg = lane >> 3;           // 0..3: which neighbor segment
    const int sub = lane & 7;            // 0..7: position within octet

    // ---- issue ALL global loads up front ----
    // concate: 8 float4 per lane; quarter-warps each cover a 128B-aligned chunk.
    const float* ce = concate + (size_t)row * (4 * TWO_D) + seg * TWO_D + sub * 4;
    float4 x[8];
#pragma unroll
    for (int j = 0; j < 8; ++j)
        x[j] = ldcs4(ce + j * 32);

    // neighbor rows: lane l owns float4 at row*128 + 4l.
    const size_t base = (size_t)row * EMBED_D + 4 * lane;
    const float4 xc = ldcs4(c_agg + base);
    const float4 xa = ldcs4(a_agg + base);
    const float4 xp = ldcs4(p_agg + base);
    const float4 xv = ldcs4(v_agg + base);

    // ---- per-lane partial dot for its segment ----
    float s = 0.0f;
#pragma unroll
    for (int j = 0; j < 8; ++j) {
        const float4 w = *reinterpret_cast<const float4*>(s_att + sub * 4 + j * 32);
        s = fmaf(x[j].x, w.x, s);
        s = fmaf(x[j].y, w.y, s);
        s = fmaf(x[j].z, w.z, s);
        s = fmaf(x[j].w, w.w, s);
    }

    // Octet butterfly: 3 shuffles -> every lane in octet o holds full dot s_o.
    s += __shfl_xor_sync(0xffffffffu, s, 4);
    s += __shfl_xor_sync(0xffffffffu, s, 2);
    s += __shfl_xor_sync(0xffffffffu, s, 1);

    // Broadcast the 4 segment dots to all lanes.
    float s0 = __shfl_sync(0xffffffffu, s, 0);
    float s1 = __shfl_sync(0xffffffffu, s, 8);
    float s2 = __shfl_sync(0xffffffffu, s, 16);
    float s3 = __shfl_sync(0xffffffffu, s, 24);

    // LeakyReLU + softmax over the 4 neighbors (redundant per lane).
    s0 = (s0 >= 0.0f) ? s0 : NEG_SLOPE * s0;
    s1 = (s1 >= 0.0f) ? s1 : NEG_SLOPE * s1;
    s2 = (s2 >= 0.0f) ? s2 : NEG_SLOPE * s2;
    s3 = (s3 >= 0.0f) ? s3 : NEG_SLOPE * s3;

    const float m = fmaxf(fmaxf(s0, s1), fmaxf(s2, s3));
    float w0 = __expf(s0 - m);
    float w1 = __expf(s1 - m);
    float w2 = __expf(s2 - m);
    float w3 = __expf(s3 - m);
    const float inv = 1.0f / (w0 + w1 + w2 + w3);
    w0 *= inv; w1 *= inv; w2 *= inv; w3 *= inv;

    // ---- weighted aggregation of the 4 neighbor rows ----
    float4 o;
    o.x = w0 * xc.x + w1 * xa.x + w2 * xp.x + w3 * xv.x;
    o.y = w0 * xc.y + w1 * xa.y + w2 * xp.y + w3 * xv.y;
    o.z = w0 * xc.z + w1 * xa.z + w2 * xp.z + w3 * xv.z;
    o.w = w0 * xc.w + w1 * xa.w + w2 * xp.w + w3 * xv.w;
    __stcs(reinterpret_cast<float4*>(out + base), o);
}

extern "C" void kernel_launch(void* const* d_in, const int* in_sizes, int n_in,
                              void* d_out, int out_size)
{
    const int*   node_type = (const int*)  d_in[0];
    const float* c_agg     = (const float*)d_in[1];
    const float* concate   = (const float*)d_in[2];
    const float* a_agg     = (const float*)d_in[3];
    const float* p_agg     = (const float*)d_in[4];
    const float* v_agg     = (const float*)d_in[5];
    const float* a_att     = (const float*)d_in[6];
    const float* p_att     = (const float*)d_in[7];
    const float* v_att     = (const float*)d_in[8];
    float* out = (float*)d_out;

    const int N = in_sizes[1] / EMBED_D;   // c_agg_batch is [N,128]

    const int threads = 256;               // 8 warps -> 8 rows per block
    const int rows_per_block = threads / 32;
    const int blocks = (N + rows_per_block - 1) / rows_per_block;
    gat_kernel<<<blocks, threads>>>(node_type, c_agg, concate,
                                    a_agg, p_agg, v_agg,
                                    a_att, p_att, v_att, out, N);
}

// round 5
// speedup vs baseline: 1.0042x; 1.0042x over previous
#include <cuda_runtime.h>
#include <cuda_bf16.h>

#define EMBED_D   128
#define TWO_D     256
#define NEG_SLOPE 0.01f

__device__ __forceinline__ float4 ldcs4(const float* p) {
    return __ldcs(reinterpret_cast<const float4*>(p));
}

// One warp per TWO rows. Lane l owns float4 slices:
//   att / concate segment part A: floats [4l .. 4l+3]
//   att / concate segment part B: floats [128+4l .. 128+4l+3]
//   output / neighbors:           floats [4l .. 4l+3] of each 128-wide row
// Two fully independent row-chains per warp double bytes-in-flight and let
// the two shuffle/softmax chains interleave.
__global__ __launch_bounds__(256) void gat_kernel(
    const int*   __restrict__ node_type,
    const float* __restrict__ c_agg,      // [N,128]
    const float* __restrict__ concate,    // [N,4,256]
    const float* __restrict__ a_agg,      // [N,128]
    const float* __restrict__ p_agg,      // [N,128]
    const float* __restrict__ v_agg,      // [N,128]
    const float* __restrict__ a_att,      // [256]
    const float* __restrict__ p_att,      // [256]
    const float* __restrict__ v_att,      // [256]
    float*       __restrict__ out,        // [N,128]
    int N)
{
    const int lane = threadIdx.x & 31;
    const int warp = (blockIdx.x * blockDim.x + threadIdx.x) >> 5;
    const int r0 = warp * 2;
    const int r1 = r0 + 1;
    if (r0 >= N) return;
    const bool has_r1 = (r1 < N);

    // Uniform branch: select attention vector by node type.
    const int nt = *node_type;
    const float* att = (nt == 1) ? a_att : (nt == 2) ? p_att : v_att;

    const float4 attA = *reinterpret_cast<const float4*>(att + 4 * lane);
    const float4 attB = *reinterpret_cast<const float4*>(att + 128 + 4 * lane);

    // ---- concate dots for both rows, accumulate on load ----
    const float* ce0 = concate + (size_t)r0 * (4 * TWO_D);
    const float* ce1 = concate + (size_t)r1 * (4 * TWO_D);

    float s0[4], s1[4];
#pragma unroll
    for (int k = 0; k < 4; ++k) {
        const float4 aA0 = ldcs4(ce0 + k * TWO_D + 4 * lane);
        const float4 aB0 = ldcs4(ce0 + k * TWO_D + 128 + 4 * lane);
        float acc0;
        acc0  = aA0.x * attA.x;
        acc0 += aA0.y * attA.y;
        acc0 += aA0.z * attA.z;
        acc0 += aA0.w * attA.w;
        acc0 += aB0.x * attB.x;
        acc0 += aB0.y * attB.y;
        acc0 += aB0.z * attB.z;
        acc0 += aB0.w * attB.w;
        s0[k] = acc0;
    }
#pragma unroll
    for (int k = 0; k < 4; ++k) {
        float acc1 = 0.0f;
        if (has_r1) {
            const float4 aA1 = ldcs4(ce1 + k * TWO_D + 4 * lane);
            const float4 aB1 = ldcs4(ce1 + k * TWO_D + 128 + 4 * lane);
            acc1  = aA1.x * attA.x;
            acc1 += aA1.y * attA.y;
            acc1 += aA1.z * attA.z;
            acc1 += aA1.w * attA.w;
            acc1 += aB1.x * attB.x;
            acc1 += aB1.y * attB.y;
            acc1 += aB1.z * attB.z;
            acc1 += aB1.w * attB.w;
        }
        s1[k] = acc1;
    }

    // ---- neighbor rows for both rows (held; in flight across shuffles) ----
    const size_t b0 = (size_t)r0 * EMBED_D + 4 * lane;
    const size_t b1 = (size_t)r1 * EMBED_D + 4 * lane;
    const float4 xc0 = ldcs4(c_agg + b0);
    const float4 xa0 = ldcs4(a_agg + b0);
    const float4 xp0 = ldcs4(p_agg + b0);
    const float4 xv0 = ldcs4(v_agg + b0);
    float4 xc1, xa1, xp1, xv1;
    if (has_r1) {
        xc1 = ldcs4(c_agg + b1);
        xa1 = ldcs4(a_agg + b1);
        xp1 = ldcs4(p_agg + b1);
        xv1 = ldcs4(v_agg + b1);
    } else {
        xc1 = xa1 = xp1 = xv1 = make_float4(0.f, 0.f, 0.f, 0.f);
    }

    // ---- two independent butterfly reductions, interleaved ----
#pragma unroll
    for (int off = 16; off > 0; off >>= 1) {
#pragma unroll
        for (int k = 0; k < 4; ++k) {
            s0[k] += __shfl_xor_sync(0xffffffffu, s0[k], off);
            s1[k] += __shfl_xor_sync(0xffffffffu, s1[k], off);
        }
    }

    // LeakyReLU + softmax per row (redundant per lane).
#pragma unroll
    for (int k = 0; k < 4; ++k) {
        s0[k] = (s0[k] >= 0.0f) ? s0[k] : NEG_SLOPE * s0[k];
        s1[k] = (s1[k] >= 0.0f) ? s1[k] : NEG_SLOPE * s1[k];
    }

    const float m0 = fmaxf(fmaxf(s0[0], s0[1]), fmaxf(s0[2], s0[3]));
    const float m1 = fmaxf(fmaxf(s1[0], s1[1]), fmaxf(s1[2], s1[3]));
    float w00 = __expf(s0[0] - m0), w01 = __expf(s0[1] - m0);
    float w02 = __expf(s0[2] - m0), w03 = __expf(s0[3] - m0);
    float w10 = __expf(s1[0] - m1), w11 = __expf(s1[1] - m1);
    float w12 = __expf(s1[2] - m1), w13 = __expf(s1[3] - m1);
    const float inv0 = 1.0f / (w00 + w01 + w02 + w03);
    const float inv1 = 1.0f / (w10 + w11 + w12 + w13);
    w00 *= inv0; w01 *= inv0; w02 *= inv0; w03 *= inv0;
    w10 *= inv1; w11 *= inv1; w12 *= inv1; w13 *= inv1;

    // ---- weighted aggregation + stores ----
    float4 o0;
    o0.x = w00 * xc0.x + w01 * xa0.x + w02 * xp0.x + w03 * xv0.x;
    o0.y = w00 * xc0.y + w01 * xa0.y + w02 * xp0.y + w03 * xv0.y;
    o0.z = w00 * xc0.z + w01 * xa0.z + w02 * xp0.z + w03 * xv0.z;
    o0.w = w00 * xc0.w + w01 * xa0.w + w02 * xp0.w + w03 * xv0.w;
    __stcs(reinterpret_cast<float4*>(out + b0), o0);

    if (has_r1) {
        float4 o1;
        o1.x = w10 * xc1.x + w11 * xa1.x + w12 * xp1.x + w13 * xv1.x;
        o1.y = w10 * xc1.y + w11 * xa1.y + w12 * xp1.y + w13 * xv1.y;
        o1.z = w10 * xc1.z + w11 * xa1.z + w12 * xp1.z + w13 * xv1.z;
        o1.w = w10 * xc1.w + w11 * xa1.w + w12 * xp1.w + w13 * xv1.w;
        __stcs(reinterpret_cast<float4*>(out + b1), o1);
    }
}

extern "C" void kernel_launch(void* const* d_in, const int* in_sizes, int n_in,
                              void* d_out, int out_size)
{
    const int*   node_type = (const int*)  d_in[0];
    const float* c_agg     = (const float*)d_in[1];
    const float* concate   = (const float*)d_in[2];
    const float* a_agg     = (const float*)d_in[3];
    const float* p_agg     = (const float*)d_in[4];
    const float* v_agg     = (const float*)d_in[5];
    const float* a_att     = (const float*)d_in[6];
    const float* p_att     = (const float*)d_in[7];
    const float* v_att     = (const float*)d_in[8];
    float* out = (float*)d_out;

    const int N = in_sizes[1] / EMBED_D;   // c_agg_batch is [N,128]

    const int threads = 256;               // 8 warps -> 16 rows per block
    const int rows_per_block = (threads / 32) * 2;
    const int blocks = (N + rows_per_block - 1) / rows_per_block;
    gat_kernel<<<blocks, threads>>>(node_type, c_agg, concate,
                                    a_agg, p_agg, v_agg,
                                    a_att, p_att, v_att, out, N);
}